// round 13
// baseline (speedup 1.0000x reference)
#include <cuda_runtime.h>
#include <cuda_fp8.h>
#include <cuda_fp16.h>
#include <cstdint>
#include <math.h>

#define T_TREES 200
#define BATCH   2048
#define D_FEAT  512
#define NNODE   64
#define NLEAF   15
#define NLEAVES 16
#define LR      0.01f

#define W_SCALE 16.0f
#define W_INV   0.0625f

#define N_ITEMS (T_TREES * (BATCH / 128))   // 3200 work items

// ---------------- device scratch (no runtime allocation allowed) -------------
__device__ uint8_t g_xf8[BATCH * D_FEAT];                    // x in e4m3
__device__ uint8_t g_wf8[(size_t)T_TREES * NNODE * D_FEAT];  // w_t e4m3, [t][n][k], x16
__device__ float   g_fT[(size_t)BATCH * T_TREES];            // f transposed [b][t]

// ---------------- helpers ------------------------------------------------------
__device__ __forceinline__ uint32_t smem_u32(const void* p) {
    uint32_t a;
    asm("{ .reg .u64 t; cvta.to.shared.u64 t, %1; cvt.u32.u64 %0, t; }" : "=r"(a) : "l"(p));
    return a;
}
#define SWZ(o) ((o) ^ (((o) >> 3) & 0x70))

__device__ __forceinline__ void cp16(uint32_t dst, const void* src) {
    asm volatile("cp.async.cg.shared.global [%0], [%1], 16;" :: "r"(dst), "l"(src));
}
#define CP_COMMIT() asm volatile("cp.async.commit_group;")

#define LDSM_X4(r, addr) \
    asm volatile("ldmatrix.sync.aligned.m8n8.x4.shared.b16 {%0,%1,%2,%3}, [%4];" \
        : "=r"((r)[0]), "=r"((r)[1]), "=r"((r)[2]), "=r"((r)[3]) : "r"(addr))

// fp8 MMA with f16 accumulate (proven 20% faster than f32-accum on sm_103 legacy pipe)
#define MMA_FP8_F16(d, a, b) \
    asm volatile("mma.sync.aligned.m16n8k32.row.col.f16.e4m3.e4m3.f16 " \
        "{%0,%1}, {%2,%3,%4,%5}, {%6,%7}, {%0,%1};" \
        : "+r"((d)[0]), "+r"((d)[1]) \
        : "r"((a)[0]), "r"((a)[1]), "r"((a)[2]), "r"((a)[3]), \
          "r"((b)[0]), "r"((b)[1]))

// f16 x f16 -> f32 MMA for the stage-2 decision GEMM
#define MMA_F16_F32(d, a0, a1, a2, a3, b0, b1) \
    asm volatile("mma.sync.aligned.m16n8k16.row.col.f32.f16.f16.f32 " \
        "{%0,%1,%2,%3}, {%4,%5,%6,%7}, {%8,%9}, {%0,%1,%2,%3};" \
        : "+f"((d)[0]), "+f"((d)[1]), "+f"((d)[2]), "+f"((d)[3]) \
        : "r"(a0), "r"(a1), "r"(a2), "r"(a3), "r"(b0), "r"(b1))

__device__ __forceinline__ float fast_sigmoid(float v) {
    float th;
    asm("tanh.approx.f32 %0, %1;" : "=f"(th) : "f"(v * 0.5f));
    return fmaf(0.5f, th, 0.5f);
}

__device__ __forceinline__ uint16_t pack_e4m3x2(float lo, float hi) {
    float2 f2; f2.x = lo; f2.y = hi;
    return (uint16_t)__nv_cvt_float2_to_fp8x2(f2, __NV_SATFINITE, __NV_E4M3);
}

// ---------------- prep kernels ------------------------------------------------
__global__ void conv_x_kernel(const float* __restrict__ x) {
    int i = (blockIdx.x * blockDim.x + threadIdx.x) * 8;
    float4 v0 = *(const float4*)(x + i);
    float4 v1 = *(const float4*)(x + i + 4);
    uint32_t lo = (uint32_t)pack_e4m3x2(v0.x, v0.y) | ((uint32_t)pack_e4m3x2(v0.z, v0.w) << 16);
    uint32_t hi = (uint32_t)pack_e4m3x2(v1.x, v1.y) | ((uint32_t)pack_e4m3x2(v1.z, v1.w) << 16);
    *(uint2*)(g_xf8 + i) = make_uint2(lo, hi);
}

// transpose w_t[t][k][n] (fp32) -> g_wf8[t][n][k] (e4m3, scaled x16)
__global__ void conv_w_kernel(const float* __restrict__ w_t) {
    __shared__ float tile[64][65];
    int t = blockIdx.y, kb = blockIdx.x * 64;
    const float* src = w_t + ((size_t)t * D_FEAT + kb) * NNODE;
    for (int i = threadIdx.x; i < 64 * 64; i += 256) {
        int r = i >> 6, n = i & 63;
        tile[r][n] = src[r * NNODE + n];
    }
    __syncthreads();
    for (int i = threadIdx.x; i < 64 * 16; i += 256) {
        int n = i >> 4, kq = (i & 15) * 4;
        uint32_t w = (uint32_t)pack_e4m3x2(tile[kq][n] * W_SCALE, tile[kq + 1][n] * W_SCALE)
                   | ((uint32_t)pack_e4m3x2(tile[kq + 2][n] * W_SCALE, tile[kq + 3][n] * W_SCALE) << 16);
        *(uint32_t*)(g_wf8 + ((size_t)t * NNODE + n) * D_FEAT + kb + kq) = w;
    }
}

// ---------------- main fused kernel (PERSISTENT) --------------------------------
// grid = 4*SMs, 128 threads (4 warps). Each CTA strides over (tree, batch-tile)
// items. Inner loop = proven R8 shape. Next item's chunk 0 is prefetched during
// the current item's last chunk, hiding the per-item cold start.
#define STAGE_BYTES 24576   // A 16KB + B 8KB
#define SMEM_DYN (2 * STAGE_BYTES)

__global__ void __launch_bounds__(128)
gbdt_main_kernel(const float* __restrict__ b_t, const float* __restrict__ w_d,
                 const float* __restrict__ b_d, const float* __restrict__ w_l,
                 const float* __restrict__ b_l)
{
    extern __shared__ char ds[];
    __shared__ __half2 s_bt2[32];          // bias pairs for 64 cols
    __shared__ __half  s_wdh[NNODE * 16];  // w_d f16, [node][leaf], col 15 zero
    __shared__ float   s_bd16[16];         // b_d padded
    __shared__ float   s_wl[NLEAVES];

    const int tid  = threadIdx.x;
    const int wid  = tid >> 5;
    const int lane = tid & 31;
    const int stride = gridDim.x;
    const uint32_t dsBase = smem_u32(ds);

    // ldmatrix lane addressing (bytes; 128B rows)
    const int a_row  = wid * 32 + (lane & 15);
    const int a_colb = (lane >> 4) * 16;
    const int b_row  = (lane & 7) + ((lane >> 4) << 3);
    const int b_colb = ((lane >> 3) & 1) * 16;

    const __half2 inv2  = __float2half2_rn(W_INV);
    const __half2 zero2 = __float2half2_rn(0.0f);
    float* ps = (float*)(ds + STAGE_BYTES);   // overlay on stage 1 (dead post-chunk-3)

    // chunk loader: item pointers + chunk index -> stage (c&1)
    auto loadChunk = [&](const uint8_t* gx, const uint8_t* gw, int c) {
        const uint32_t aB = dsBase + (c & 1) * STAGE_BYTES;
        const uint32_t bB = aB + 16384;
        const int kc = c * 128;
        #pragma unroll
        for (int it = 0; it < 8; it++) {
            int ui = tid + it * 128;
            int r = ui >> 3, seg = ui & 7;
            cp16(aB + SWZ(r * 128 + seg * 16), gx + (size_t)r * D_FEAT + kc + seg * 16);
        }
        #pragma unroll
        for (int it = 0; it < 4; it++) {
            int ui = tid + it * 128;
            int r = ui >> 3, seg = ui & 7;
            cp16(bB + SWZ(r * 128 + seg * 16), gw + (size_t)r * D_FEAT + kc + seg * 16);
        }
        CP_COMMIT();
    };

    int wk = blockIdx.x;
    if (wk >= N_ITEMS) return;

    // prologue: chunk 0 of first item
    {
        const uint8_t* gx0 = g_xf8 + (size_t)(wk & 15) * 128 * D_FEAT;
        const uint8_t* gw0 = g_wf8 + (size_t)(wk >> 4) * NNODE * D_FEAT;
        loadChunk(gx0, gw0, 0);
    }

    for (; wk < N_ITEMS; wk += stride) {
        const int t  = wk >> 4;
        const int rb = (wk & 15) << 7;
        const int nwk = wk + stride;
        const bool hasNext = (nwk < N_ITEMS);
        const uint8_t* gx = g_xf8 + (size_t)rb * D_FEAT;
        const uint8_t* gw = g_wf8 + (size_t)t * NNODE * D_FEAT;

        // per-tree small weights (latency hidden under in-flight chunk 0)
        if (tid < 32) {
            s_bt2[tid] = __floats2half2_rn(b_t[t * NNODE + 2 * tid],
                                           b_t[t * NNODE + 2 * tid + 1]);
        }
        for (int i = tid; i < NNODE * 16; i += 128) {
            int node = i >> 4, leaf = i & 15;
            s_wdh[i] = (leaf < NLEAF)
                ? __float2half(w_d[(size_t)t * NNODE * NLEAF + node * NLEAF + leaf])
                : __half(0.0f);
        }
        if (tid < 16)      s_bd16[tid] = (tid < NLEAF) ? b_d[t * NLEAF + tid] : 0.0f;
        else if (tid < 32) s_wl[tid - 16] = w_l[t * NLEAVES + tid - 16];

        uint32_t acc[2][8][2];
        #pragma unroll
        for (int mt = 0; mt < 2; mt++)
            #pragma unroll
            for (int nt = 0; nt < 8; nt++) { acc[mt][nt][0] = 0u; acc[mt][nt][1] = 0u; }

        for (int c = 0; c < 4; c++) {
            if (c < 3) {
                loadChunk(gx, gw, c + 1);
                asm volatile("cp.async.wait_group 1;");
            } else if (hasNext) {
                // prefetch next item's chunk 0 into stage 0 (freed at c=2 exit sync)
                const uint8_t* gxn = g_xf8 + (size_t)((nwk & 15) << 7) * D_FEAT;
                const uint8_t* gwn = g_wf8 + (size_t)(nwk >> 4) * NNODE * D_FEAT;
                loadChunk(gxn, gwn, 0);
                asm volatile("cp.async.wait_group 1;");
            } else {
                asm volatile("cp.async.wait_group 0;");
            }
            __syncthreads();

            const uint32_t aB = dsBase + (c & 1) * STAGE_BYTES;
            const uint32_t bB = aB + 16384;
            #pragma unroll
            for (int ks = 0; ks < 4; ks++) {
                const int kk = ks * 32;
                uint32_t afr[2][4];
                #pragma unroll
                for (int mt = 0; mt < 2; mt++)
                    LDSM_X4(afr[mt], aB + SWZ((a_row + mt * 16) * 128 + kk + a_colb));
                uint32_t bfr[8][2];
                #pragma unroll
                for (int nq = 0; nq < 4; nq++) {
                    uint32_t r4[4];
                    LDSM_X4(r4, bB + SWZ((b_row + nq * 16) * 128 + kk + b_colb));
                    bfr[2 * nq][0]     = r4[0]; bfr[2 * nq][1]     = r4[1];
                    bfr[2 * nq + 1][0] = r4[2]; bfr[2 * nq + 1][1] = r4[3];
                }
                #pragma unroll
                for (int mt = 0; mt < 2; mt++)
                    #pragma unroll
                    for (int nt = 0; nt < 8; nt++)
                        MMA_FP8_F16(acc[mt][nt], afr[mt], bfr[nt]);
            }
            if (c < 3) __syncthreads();
        }

        // all warps done reading stage 1 (chunk 3) before ps overlays it
        __syncthreads();

        // ---------------- epilogue (register-resident) --------------------------
        // 1) h = relu(acc/16 + bias) in f16x2
        #pragma unroll
        for (int mt = 0; mt < 2; mt++)
            #pragma unroll
            for (int nt = 0; nt < 8; nt++) {
                __half2 bias = s_bt2[nt * 4 + (lane & 3)];
                #pragma unroll
                for (int r = 0; r < 2; r++) {
                    __half2 v = *(__half2*)&acc[mt][nt][r];
                    v = __hmax2(__hfma2(v, inv2, bias), zero2);
                    acc[mt][nt][r] = *(uint32_t*)&v;
                }
            }

        // 2) B fragments of w_d
        uint32_t bw[2][4][2];
        {
            const int n = lane >> 2;
            const int kb = (lane & 3) * 2;
            #pragma unroll
            for (int nt2 = 0; nt2 < 2; nt2++)
                #pragma unroll
                for (int ks = 0; ks < 4; ks++) {
                    int k0 = ks * 16 + kb;
                    int nn = nt2 * 8 + n;
                    __half2 lo = __halves2half2(s_wdh[k0 * 16 + nn],       s_wdh[(k0 + 1) * 16 + nn]);
                    __half2 hi = __halves2half2(s_wdh[(k0 + 8) * 16 + nn], s_wdh[(k0 + 9) * 16 + nn]);
                    bw[nt2][ks][0] = *(uint32_t*)&lo;
                    bw[nt2][ks][1] = *(uint32_t*)&hi;
                }
        }

        // 3) logits via mma.m16n8k16
        float lg[2][2][4];
        {
            const int col = (lane & 3) * 2;
            #pragma unroll
            for (int mt = 0; mt < 2; mt++)
                #pragma unroll
                for (int nt2 = 0; nt2 < 2; nt2++) {
                    lg[mt][nt2][0] = s_bd16[nt2 * 8 + col];
                    lg[mt][nt2][1] = s_bd16[nt2 * 8 + col + 1];
                    lg[mt][nt2][2] = lg[mt][nt2][0];
                    lg[mt][nt2][3] = lg[mt][nt2][1];
                }
            #pragma unroll
            for (int mt = 0; mt < 2; mt++)
                #pragma unroll
                for (int ks = 0; ks < 4; ks++)
                    #pragma unroll
                    for (int nt2 = 0; nt2 < 2; nt2++)
                        MMA_F16_F32(lg[mt][nt2],
                                    acc[mt][2 * ks][0], acc[mt][2 * ks][1],
                                    acc[mt][2 * ks + 1][0], acc[mt][2 * ks + 1][1],
                                    bw[nt2][ks][0], bw[nt2][ks][1]);
        }

        // 4) sigmoid + warp-local exchange (ps on stage 1)
        {
            const int g   = lane >> 2;
            const int col = (lane & 3) * 2;
            #pragma unroll
            for (int mt = 0; mt < 2; mt++) {
                int r0 = wid * 32 + mt * 16 + g;
                #pragma unroll
                for (int nt2 = 0; nt2 < 2; nt2++) {
                    int cc = nt2 * 8 + col;
                    ps[r0 * 17 + cc]           = fast_sigmoid(lg[mt][nt2][0]);
                    ps[r0 * 17 + cc + 1]       = fast_sigmoid(lg[mt][nt2][1]);
                    ps[(r0 + 8) * 17 + cc]     = fast_sigmoid(lg[mt][nt2][2]);
                    ps[(r0 + 8) * 17 + cc + 1] = fast_sigmoid(lg[mt][nt2][3]);
                }
            }
        }
        __syncwarp();

        // 5) routing + tanh, one row per thread
        {
            const float* prow = &ps[tid * 17];
            float p[NLEAF];
            #pragma unroll
            for (int j = 0; j < NLEAF; j++) p[j] = prow[j];
            float facc = 0.0f;
            #pragma unroll
            for (int l = 0; l < NLEAVES; l++) {
                int node = 0;
                float m = 1.0f;
                #pragma unroll
                for (int d = 0; d < 4; d++) {
                    int bit = (l >> (3 - d)) & 1;
                    float pv = p[node];
                    m *= bit ? (1.0f - pv) : pv;
                    node = 2 * node + 1 + bit;
                }
                facc = fmaf(m, s_wl[l], facc);
            }
            float f = tanhf(facc + b_l[t]);
            g_fT[(size_t)(rb + tid) * T_TREES + t] = f;
        }

        // protect ps (stage 1) + smem weights before next item's loads/writes
        __syncthreads();
    }
}

// ---------------- cumsum: one warp per batch row, MLP-prefetched ---------------
__global__ void gbdt_cumsum_kernel(const float* __restrict__ f0,
                                   float* __restrict__ out)
{
    int gwarp = (blockIdx.x * blockDim.x + threadIdx.x) >> 5;
    int lane  = threadIdx.x & 31;
    if (gwarp >= BATCH) return;

    float vals[7];
    #pragma unroll
    for (int i = 0; i < 7; i++) {
        int tt = i * 32 + lane;
        vals[i] = (tt < T_TREES) ? LR * g_fT[(size_t)gwarp * T_TREES + tt] : 0.0f;
    }

    float run = f0[0];
    if (lane == 0) out[(size_t)gwarp * (T_TREES + 1)] = run;
    #pragma unroll
    for (int i = 0; i < 7; i++) {
        float v = vals[i];
        #pragma unroll
        for (int off = 1; off < 32; off <<= 1) {
            float nv = __shfl_up_sync(0xFFFFFFFFu, v, off);
            if (lane >= off) v += nv;
        }
        int tt = i * 32 + lane;
        if (tt < T_TREES) out[(size_t)gwarp * (T_TREES + 1) + 1 + tt] = run + v;
        run += __shfl_sync(0xFFFFFFFFu, v, 31);
    }
}

// ---------------- launcher ------------------------------------------------------
extern "C" void kernel_launch(void* const* d_in, const int* in_sizes, int n_in,
                              void* d_out, int out_size)
{
    const float* x   = (const float*)d_in[0];
    const float* w_t = (const float*)d_in[2];
    const float* b_t = (const float*)d_in[3];
    const float* w_d = (const float*)d_in[4];
    const float* b_d = (const float*)d_in[5];
    const float* w_l = (const float*)d_in[6];
    const float* b_l = (const float*)d_in[7];
    const float* f_0 = (const float*)d_in[8];
    float* out = (float*)d_out;

    static int grid_main = 0;
    if (grid_main == 0) {
        cudaFuncSetAttribute(gbdt_main_kernel,
                             cudaFuncAttributeMaxDynamicSharedMemorySize, SMEM_DYN);
        int sms = 0;
        cudaDeviceGetAttribute(&sms, cudaDevAttrMultiProcessorCount, 0);
        if (sms <= 0) sms = 148;
        grid_main = sms * 4;                 // one exact wave at 4 CTAs/SM
        if (grid_main > N_ITEMS) grid_main = N_ITEMS;
    }

    conv_x_kernel<<<(BATCH * D_FEAT / 8 + 255) / 256, 256>>>(x);
    conv_w_kernel<<<dim3(D_FEAT / 64, T_TREES), 256>>>(w_t);
    gbdt_main_kernel<<<grid_main, 128, SMEM_DYN>>>(b_t, w_d, b_d, w_l, b_l);
    gbdt_cumsum_kernel<<<(BATCH * 32 + 255) / 256, 256>>>(f_0, out);
}

// round 14
// speedup vs baseline: 1.2599x; 1.2599x over previous
#include <cuda_runtime.h>
#include <cuda_fp8.h>
#include <cuda_fp16.h>
#include <cstdint>
#include <math.h>

#define T_TREES 200
#define BATCH   2048
#define D_FEAT  512
#define NNODE   64
#define NLEAF   15
#define NLEAVES 16
#define LR      0.01f

#define W_SCALE 16.0f
#define W_INV   0.0625f

// ---------------- device scratch (no runtime allocation allowed) -------------
__device__ uint8_t g_xf8[BATCH * D_FEAT];                    // x in e4m3
__device__ uint8_t g_wf8[(size_t)T_TREES * NNODE * D_FEAT];  // w_t e4m3, [t][n][k], x16
__device__ float   g_fT[(size_t)BATCH * T_TREES];            // f transposed [b][t]

// ---------------- helpers ------------------------------------------------------
__device__ __forceinline__ uint32_t smem_u32(const void* p) {
    uint32_t a;
    asm("{ .reg .u64 t; cvta.to.shared.u64 t, %1; cvt.u32.u64 %0, t; }" : "=r"(a) : "l"(p));
    return a;
}
#define SWZ(o) ((o) ^ (((o) >> 3) & 0x70))

__device__ __forceinline__ void cp16(uint32_t dst, const void* src) {
    asm volatile("cp.async.cg.shared.global [%0], [%1], 16;" :: "r"(dst), "l"(src));
}
#define CP_COMMIT() asm volatile("cp.async.commit_group;")

#define LDSM_X4(r, addr) \
    asm volatile("ldmatrix.sync.aligned.m8n8.x4.shared.b16 {%0,%1,%2,%3}, [%4];" \
        : "=r"((r)[0]), "=r"((r)[1]), "=r"((r)[2]), "=r"((r)[3]) : "r"(addr))

// fp8 MMA with f16 accumulate (proven 20% faster than f32-accum on sm_103 legacy pipe)
#define MMA_FP8_F16(d, a, b) \
    asm volatile("mma.sync.aligned.m16n8k32.row.col.f16.e4m3.e4m3.f16 " \
        "{%0,%1}, {%2,%3,%4,%5}, {%6,%7}, {%0,%1};" \
        : "+r"((d)[0]), "+r"((d)[1]) \
        : "r"((a)[0]), "r"((a)[1]), "r"((a)[2]), "r"((a)[3]), \
          "r"((b)[0]), "r"((b)[1]))

// f16 x f16 -> f32 MMA for the stage-2 decision GEMM
#define MMA_F16_F32(d, a0, a1, a2, a3, b0, b1) \
    asm volatile("mma.sync.aligned.m16n8k16.row.col.f32.f16.f16.f32 " \
        "{%0,%1,%2,%3}, {%4,%5,%6,%7}, {%8,%9}, {%0,%1,%2,%3};" \
        : "+f"((d)[0]), "+f"((d)[1]), "+f"((d)[2]), "+f"((d)[3]) \
        : "r"(a0), "r"(a1), "r"(a2), "r"(a3), "r"(b0), "r"(b1))

__device__ __forceinline__ float fast_sigmoid(float v) {
    float th;
    asm("tanh.approx.f32 %0, %1;" : "=f"(th) : "f"(v * 0.5f));
    return fmaf(0.5f, th, 0.5f);
}

__device__ __forceinline__ uint16_t pack_e4m3x2(float lo, float hi) {
    float2 f2; f2.x = lo; f2.y = hi;
    return (uint16_t)__nv_cvt_float2_to_fp8x2(f2, __NV_SATFINITE, __NV_E4M3);
}

// ---------------- fused prep kernel --------------------------------------------
// blocks [0, 512): convert x (fp32 -> e4m3).
// blocks [512, 2112): transpose+convert w_t[t][k][n] -> g_wf8[t][n][k] (e4m3 x16).
#define XBLOCKS (BATCH * D_FEAT / 8 / 256)   // 512

__global__ void conv_prep_kernel(const float* __restrict__ x,
                                 const float* __restrict__ w_t) {
    __shared__ float tile[64][65];
    if (blockIdx.x < XBLOCKS) {
        int i = (blockIdx.x * 256 + threadIdx.x) * 8;
        float4 v0 = *(const float4*)(x + i);
        float4 v1 = *(const float4*)(x + i + 4);
        uint32_t lo = (uint32_t)pack_e4m3x2(v0.x, v0.y) | ((uint32_t)pack_e4m3x2(v0.z, v0.w) << 16);
        uint32_t hi = (uint32_t)pack_e4m3x2(v1.x, v1.y) | ((uint32_t)pack_e4m3x2(v1.z, v1.w) << 16);
        *(uint2*)(g_xf8 + i) = make_uint2(lo, hi);
        return;
    }
    int bid = blockIdx.x - XBLOCKS;
    int t = bid >> 3, kb = (bid & 7) * 64;
    const float* src = w_t + ((size_t)t * D_FEAT + kb) * NNODE;
    for (int i = threadIdx.x; i < 64 * 64; i += 256) {
        int r = i >> 6, n = i & 63;
        tile[r][n] = src[r * NNODE + n];
    }
    __syncthreads();
    for (int i = threadIdx.x; i < 64 * 16; i += 256) {
        int n = i >> 4, kq = (i & 15) * 4;
        uint32_t w = (uint32_t)pack_e4m3x2(tile[kq][n] * W_SCALE, tile[kq + 1][n] * W_SCALE)
                   | ((uint32_t)pack_e4m3x2(tile[kq + 2][n] * W_SCALE, tile[kq + 3][n] * W_SCALE) << 16);
        *(uint32_t*)(g_wf8 + ((size_t)t * NNODE + n) * D_FEAT + kb + kq) = w;
    }
}

// ---------------- main fused kernel -------------------------------------------
// grid (16, 200), 128 threads (4 warps). CTA: tree t, batch rows [rb, rb+128).
// Proven-optimal shape: M=128, double-buffered 24KB stages, 4 CTAs/SM.
// Stage 1: [128x512] e4m3 @ [512x64] e4m3 -> f16 accum (mma.m16n8k32).
// Stage 2: h (register f16, C->A fragment reuse) @ w_d f16 -> f32 (mma.m16n8k16).
#define STAGE_BYTES 24576   // A 16KB + B 8KB
#define SMEM_DYN (2 * STAGE_BYTES)

__global__ void __launch_bounds__(128)
gbdt_main_kernel(const float* __restrict__ b_t, const float* __restrict__ w_d,
                 const float* __restrict__ b_d, const float* __restrict__ w_l,
                 const float* __restrict__ b_l)
{
    extern __shared__ char ds[];
    __shared__ __half2 s_bt2[32];          // bias pairs for 64 cols
    __shared__ __half  s_wdh[NNODE * 16];  // w_d f16, [node][leaf], col 15 zero
    __shared__ float   s_bd16[16];         // b_d padded
    __shared__ float   s_wl[NLEAVES];

    const int t    = blockIdx.y;
    const int rb   = blockIdx.x * 128;
    const int tid  = threadIdx.x;
    const int wid  = tid >> 5;
    const int lane = tid & 31;
    const uint32_t dsBase = smem_u32(ds);

    // per-tree small weights
    if (tid < 32) {
        float b0 = b_t[t * NNODE + 2 * tid];
        float b1 = b_t[t * NNODE + 2 * tid + 1];
        s_bt2[tid] = __floats2half2_rn(b0, b1);
    }
    for (int i = tid; i < NNODE * 16; i += 128) {
        int node = i >> 4, leaf = i & 15;
        s_wdh[i] = (leaf < NLEAF) ? __float2half(w_d[(size_t)t * NNODE * NLEAF + node * NLEAF + leaf])
                                  : __half(0.0f);
    }
    if (tid < 16)      s_bd16[tid] = (tid < NLEAF) ? b_d[t * NLEAF + tid] : 0.0f;
    else if (tid < 32) s_wl[tid - 16] = w_l[t * NLEAVES + tid - 16];

    // f16x2 accumulators: [mt][nt][2]
    uint32_t acc[2][8][2];
    #pragma unroll
    for (int mt = 0; mt < 2; mt++)
        #pragma unroll
        for (int nt = 0; nt < 8; nt++) { acc[mt][nt][0] = 0u; acc[mt][nt][1] = 0u; }

    // ldmatrix lane addressing (bytes; 128B rows)
    const int a_row  = wid * 32 + (lane & 15);
    const int a_colb = (lane >> 4) * 16;
    const int b_row  = (lane & 7) + ((lane >> 4) << 3);
    const int b_colb = ((lane >> 3) & 1) * 16;

    const uint8_t* gx = g_xf8 + (size_t)rb * D_FEAT;
    const uint8_t* gw = g_wf8 + (size_t)t * NNODE * D_FEAT;

    auto loadChunk = [&](int c) {
        const uint32_t aB = dsBase + (c & 1) * STAGE_BYTES;
        const uint32_t bB = aB + 16384;
        const int kc = c * 128;
        #pragma unroll
        for (int it = 0; it < 8; it++) {
            int ui = tid + it * 128;
            int r = ui >> 3, seg = ui & 7;
            cp16(aB + SWZ(r * 128 + seg * 16), gx + (size_t)r * D_FEAT + kc + seg * 16);
        }
        #pragma unroll
        for (int it = 0; it < 4; it++) {
            int ui = tid + it * 128;
            int r = ui >> 3, seg = ui & 7;
            cp16(bB + SWZ(r * 128 + seg * 16), gw + (size_t)r * D_FEAT + kc + seg * 16);
        }
        CP_COMMIT();
    };

    loadChunk(0);
    for (int c = 0; c < 4; c++) {
        if (c < 3) {
            loadChunk(c + 1);
            asm volatile("cp.async.wait_group 1;");
        } else {
            asm volatile("cp.async.wait_group 0;");
        }
        __syncthreads();

        const uint32_t aB = dsBase + (c & 1) * STAGE_BYTES;
        const uint32_t bB = aB + 16384;
        #pragma unroll
        for (int ks = 0; ks < 4; ks++) {
            const int kk = ks * 32;
            uint32_t afr[2][4];
            #pragma unroll
            for (int mt = 0; mt < 2; mt++)
                LDSM_X4(afr[mt], aB + SWZ((a_row + mt * 16) * 128 + kk + a_colb));
            uint32_t bfr[8][2];
            #pragma unroll
            for (int nq = 0; nq < 4; nq++) {
                uint32_t r4[4];
                LDSM_X4(r4, bB + SWZ((b_row + nq * 16) * 128 + kk + b_colb));
                bfr[2 * nq][0]     = r4[0]; bfr[2 * nq][1]     = r4[1];
                bfr[2 * nq + 1][0] = r4[2]; bfr[2 * nq + 1][1] = r4[3];
            }
            #pragma unroll
            for (int mt = 0; mt < 2; mt++)
                #pragma unroll
                for (int nt = 0; nt < 8; nt++)
                    MMA_FP8_F16(acc[mt][nt], afr[mt], bfr[nt]);
        }
        if (c < 3) __syncthreads();
    }

    // ---------------- epilogue (register-resident) ------------------------------
    // 1) h = relu(acc * 1/16 + bias) in f16x2, in place (C->A fragment layout reuse)
    const __half2 inv2  = __float2half2_rn(W_INV);
    const __half2 zero2 = __float2half2_rn(0.0f);
    #pragma unroll
    for (int mt = 0; mt < 2; mt++)
        #pragma unroll
        for (int nt = 0; nt < 8; nt++) {
            __half2 bias = s_bt2[nt * 4 + (lane & 3)];
            #pragma unroll
            for (int r = 0; r < 2; r++) {
                __half2 v = *(__half2*)&acc[mt][nt][r];
                v = __hmax2(__hfma2(v, inv2, bias), zero2);
                acc[mt][nt][r] = *(uint32_t*)&v;
            }
        }

    // 2) B fragments of w_d (k=node 64, n=leaf 16): bw[nt2][ks][2]
    uint32_t bw[2][4][2];
    {
        const int n = lane >> 2;
        const int kb = (lane & 3) * 2;
        #pragma unroll
        for (int nt2 = 0; nt2 < 2; nt2++)
            #pragma unroll
            for (int ks = 0; ks < 4; ks++) {
                int k0 = ks * 16 + kb;
                int nn = nt2 * 8 + n;
                __half2 lo = __halves2half2(s_wdh[k0 * 16 + nn],       s_wdh[(k0 + 1) * 16 + nn]);
                __half2 hi = __halves2half2(s_wdh[(k0 + 8) * 16 + nn], s_wdh[(k0 + 9) * 16 + nn]);
                bw[nt2][ks][0] = *(uint32_t*)&lo;
                bw[nt2][ks][1] = *(uint32_t*)&hi;
            }
    }

    // 3) logits = h @ w_d + b_d via mma.m16n8k16 (f32 accum)
    float lg[2][2][4];
    {
        const int col = (lane & 3) * 2;
        #pragma unroll
        for (int mt = 0; mt < 2; mt++)
            #pragma unroll
            for (int nt2 = 0; nt2 < 2; nt2++) {
                lg[mt][nt2][0] = s_bd16[nt2 * 8 + col];
                lg[mt][nt2][1] = s_bd16[nt2 * 8 + col + 1];
                lg[mt][nt2][2] = lg[mt][nt2][0];
                lg[mt][nt2][3] = lg[mt][nt2][1];
            }
        #pragma unroll
        for (int mt = 0; mt < 2; mt++)
            #pragma unroll
            for (int ks = 0; ks < 4; ks++) {
                #pragma unroll
                for (int nt2 = 0; nt2 < 2; nt2++)
                    MMA_F16_F32(lg[mt][nt2],
                                acc[mt][2 * ks][0], acc[mt][2 * ks][1],
                                acc[mt][2 * ks + 1][0], acc[mt][2 * ks + 1][1],
                                bw[nt2][ks][0], bw[nt2][ks][1]);
            }
    }

    // 4) sigmoid + warp-local exchange through smem (overlays dead stage-0 buffer)
    float* ps = (float*)ds;   // [128][17]
    {
        const int g   = lane >> 2;
        const int col = (lane & 3) * 2;
        #pragma unroll
        for (int mt = 0; mt < 2; mt++) {
            int r0 = wid * 32 + mt * 16 + g;
            #pragma unroll
            for (int nt2 = 0; nt2 < 2; nt2++) {
                int cc = nt2 * 8 + col;
                ps[r0 * 17 + cc]           = fast_sigmoid(lg[mt][nt2][0]);
                ps[r0 * 17 + cc + 1]       = fast_sigmoid(lg[mt][nt2][1]);
                ps[(r0 + 8) * 17 + cc]     = fast_sigmoid(lg[mt][nt2][2]);
                ps[(r0 + 8) * 17 + cc + 1] = fast_sigmoid(lg[mt][nt2][3]);
            }
        }
    }
    __syncwarp();

    // 5) routing + tanh, one row per thread (row == tid, warp-local)
    {
        const float* prow = &ps[tid * 17];
        float p[NLEAF];
        #pragma unroll
        for (int j = 0; j < NLEAF; j++) p[j] = prow[j];
        float facc = 0.0f;
        #pragma unroll
        for (int l = 0; l < NLEAVES; l++) {
            int node = 0;
            float m = 1.0f;
            #pragma unroll
            for (int d = 0; d < 4; d++) {
                int bit = (l >> (3 - d)) & 1;
                float pv = p[node];
                m *= bit ? (1.0f - pv) : pv;
                node = 2 * node + 1 + bit;
            }
            facc = fmaf(m, s_wl[l], facc);
        }
        float f = tanhf(facc + b_l[t]);
        g_fT[(size_t)(rb + tid) * T_TREES + t] = f;
    }
}

// ---------------- cumsum: one warp per batch row, MLP-prefetched ---------------
__global__ void gbdt_cumsum_kernel(const float* __restrict__ f0,
                                   float* __restrict__ out)
{
    int gwarp = (blockIdx.x * blockDim.x + threadIdx.x) >> 5;
    int lane  = threadIdx.x & 31;
    if (gwarp >= BATCH) return;

    float vals[7];
    #pragma unroll
    for (int i = 0; i < 7; i++) {
        int tt = i * 32 + lane;
        vals[i] = (tt < T_TREES) ? LR * g_fT[(size_t)gwarp * T_TREES + tt] : 0.0f;
    }

    float run = f0[0];
    if (lane == 0) out[(size_t)gwarp * (T_TREES + 1)] = run;
    #pragma unroll
    for (int i = 0; i < 7; i++) {
        float v = vals[i];
        #pragma unroll
        for (int off = 1; off < 32; off <<= 1) {
            float nv = __shfl_up_sync(0xFFFFFFFFu, v, off);
            if (lane >= off) v += nv;
        }
        int tt = i * 32 + lane;
        if (tt < T_TREES) out[(size_t)gwarp * (T_TREES + 1) + 1 + tt] = run + v;
        run += __shfl_sync(0xFFFFFFFFu, v, 31);
    }
}

// ---------------- launcher ------------------------------------------------------
extern "C" void kernel_launch(void* const* d_in, const int* in_sizes, int n_in,
                              void* d_out, int out_size)
{
    const float* x   = (const float*)d_in[0];
    const float* w_t = (const float*)d_in[2];
    const float* b_t = (const float*)d_in[3];
    const float* w_d = (const float*)d_in[4];
    const float* b_d = (const float*)d_in[5];
    const float* w_l = (const float*)d_in[6];
    const float* b_l = (const float*)d_in[7];
    const float* f_0 = (const float*)d_in[8];
    float* out = (float*)d_out;

    static bool attr_set = false;
    if (!attr_set) {
        cudaFuncSetAttribute(gbdt_main_kernel,
                             cudaFuncAttributeMaxDynamicSharedMemorySize, SMEM_DYN);
        attr_set = true;
    }

    conv_prep_kernel<<<XBLOCKS + 8 * T_TREES, 256>>>(x, w_t);
    gbdt_main_kernel<<<dim3(BATCH / 128, T_TREES), 128, SMEM_DYN>>>(b_t, w_d, b_d, w_l, b_l);
    gbdt_cumsum_kernel<<<(BATCH * 32 + 255) / 256, 256>>>(f_0, out);
}

// round 15
// speedup vs baseline: 1.3234x; 1.0504x over previous
#include <cuda_runtime.h>
#include <cuda_fp8.h>
#include <cuda_fp16.h>
#include <cstdint>
#include <math.h>

#define T_TREES 200
#define BATCH   2048
#define D_FEAT  512
#define NNODE   64
#define NLEAF   15
#define NLEAVES 16
#define LR      0.01f

#define W_SCALE 16.0f
#define W_INV   0.0625f

// ---------------- device scratch (no runtime allocation allowed) -------------
__device__ uint8_t g_xf8[BATCH * D_FEAT];                    // x in e4m3
__device__ uint8_t g_wf8[(size_t)T_TREES * NNODE * D_FEAT];  // w_t e4m3, [t][n][k], x16
__device__ float   g_fT[(size_t)BATCH * T_TREES];            // f transposed [b][t]

// ---------------- helpers ------------------------------------------------------
__device__ __forceinline__ uint32_t smem_u32(const void* p) {
    uint32_t a;
    asm("{ .reg .u64 t; cvta.to.shared.u64 t, %1; cvt.u32.u64 %0, t; }" : "=r"(a) : "l"(p));
    return a;
}
#define SWZ(o) ((o) ^ (((o) >> 3) & 0x70))

__device__ __forceinline__ void cp16(uint32_t dst, const void* src) {
    asm volatile("cp.async.cg.shared.global [%0], [%1], 16;" :: "r"(dst), "l"(src));
}
#define CP_COMMIT() asm volatile("cp.async.commit_group;")

#define LDSM_X4(r, addr) \
    asm volatile("ldmatrix.sync.aligned.m8n8.x4.shared.b16 {%0,%1,%2,%3}, [%4];" \
        : "=r"((r)[0]), "=r"((r)[1]), "=r"((r)[2]), "=r"((r)[3]) : "r"(addr))

// fp8 MMA with f16 accumulate (proven 20% faster than f32-accum on sm_103 legacy pipe)
#define MMA_FP8_F16(d, a, b) \
    asm volatile("mma.sync.aligned.m16n8k32.row.col.f16.e4m3.e4m3.f16 " \
        "{%0,%1}, {%2,%3,%4,%5}, {%6,%7}, {%0,%1};" \
        : "+r"((d)[0]), "+r"((d)[1]) \
        : "r"((a)[0]), "r"((a)[1]), "r"((a)[2]), "r"((a)[3]), \
          "r"((b)[0]), "r"((b)[1]))

// f16 x f16 -> f32 MMA for the stage-2 decision GEMM
#define MMA_F16_F32(d, a0, a1, a2, a3, b0, b1) \
    asm volatile("mma.sync.aligned.m16n8k16.row.col.f32.f16.f16.f32 " \
        "{%0,%1,%2,%3}, {%4,%5,%6,%7}, {%8,%9}, {%0,%1,%2,%3};" \
        : "+f"((d)[0]), "+f"((d)[1]), "+f"((d)[2]), "+f"((d)[3]) \
        : "r"(a0), "r"(a1), "r"(a2), "r"(a3), "r"(b0), "r"(b1))

__device__ __forceinline__ float fast_sigmoid(float v) {
    float th;
    asm("tanh.approx.f32 %0, %1;" : "=f"(th) : "f"(v * 0.5f));
    return fmaf(0.5f, th, 0.5f);
}

__device__ __forceinline__ uint16_t pack_e4m3x2(float lo, float hi) {
    float2 f2; f2.x = lo; f2.y = hi;
    return (uint16_t)__nv_cvt_float2_to_fp8x2(f2, __NV_SATFINITE, __NV_E4M3);
}

// ---------------- fused prep kernel --------------------------------------------
// blocks [0, 512): convert x (fp32 -> e4m3), 8 values/thread.
// blocks [512, 2112): smem-free w transpose+convert. Thread = (t, n, 16-k chunk):
//   16 warp-coalesced loads of w_t[k][n] (same n, consecutive k) already form the
//   [n][k] slice in registers -> pack -> one aligned uint4 store. MLP=16, no syncs.
#define XBLOCKS (BATCH * D_FEAT / 8 / 256)            // 512
#define WBLOCKS (T_TREES * NNODE * 32 / 256)          // 1600

__global__ void conv_prep_kernel(const float* __restrict__ x,
                                 const float* __restrict__ w_t) {
    if (blockIdx.x < XBLOCKS) {
        int i = (blockIdx.x * 256 + threadIdx.x) * 8;
        float4 v0 = *(const float4*)(x + i);
        float4 v1 = *(const float4*)(x + i + 4);
        uint32_t lo = (uint32_t)pack_e4m3x2(v0.x, v0.y) | ((uint32_t)pack_e4m3x2(v0.z, v0.w) << 16);
        uint32_t hi = (uint32_t)pack_e4m3x2(v1.x, v1.y) | ((uint32_t)pack_e4m3x2(v1.z, v1.w) << 16);
        *(uint2*)(g_xf8 + i) = make_uint2(lo, hi);
        return;
    }
    int o   = (blockIdx.x - XBLOCKS) * 256 + threadIdx.x;  // 0 .. 409599
    int n   = o & 63;
    int k16 = (o >> 6) & 31;
    int t   = o >> 11;

    const float* src = w_t + ((size_t)t * D_FEAT + k16 * 16) * NNODE + n;
    float v[16];
    #pragma unroll
    for (int j = 0; j < 16; j++) v[j] = src[j * NNODE] * W_SCALE;

    uint32_t outw[4];
    #pragma unroll
    for (int q = 0; q < 4; q++) {
        outw[q] = (uint32_t)pack_e4m3x2(v[4 * q],     v[4 * q + 1])
                | ((uint32_t)pack_e4m3x2(v[4 * q + 2], v[4 * q + 3]) << 16);
    }
    *(uint4*)(g_wf8 + ((size_t)t * NNODE + n) * D_FEAT + k16 * 16) = *(uint4*)outw;
}

// ---------------- main fused kernel -------------------------------------------
// grid (16, 200), 128 threads (4 warps). CTA: tree t, batch rows [rb, rb+128).
// Proven-optimal shape: M=128, double-buffered 24KB stages, 4 CTAs/SM.
// Stage 1: [128x512] e4m3 @ [512x64] e4m3 -> f16 accum (mma.m16n8k32).
// Stage 2: h (register f16, C->A fragment reuse) @ w_d f16 -> f32 (mma.m16n8k16).
#define STAGE_BYTES 24576   // A 16KB + B 8KB
#define SMEM_DYN (2 * STAGE_BYTES)

__global__ void __launch_bounds__(128)
gbdt_main_kernel(const float* __restrict__ b_t, const float* __restrict__ w_d,
                 const float* __restrict__ b_d, const float* __restrict__ w_l,
                 const float* __restrict__ b_l)
{
    extern __shared__ char ds[];
    __shared__ __half2 s_bt2[32];          // bias pairs for 64 cols
    __shared__ __half  s_wdh[NNODE * 16];  // w_d f16, [node][leaf], col 15 zero
    __shared__ float   s_bd16[16];         // b_d padded
    __shared__ float   s_wl[NLEAVES];

    const int t    = blockIdx.y;
    const int rb   = blockIdx.x * 128;
    const int tid  = threadIdx.x;
    const int wid  = tid >> 5;
    const int lane = tid & 31;
    const uint32_t dsBase = smem_u32(ds);

    // per-tree small weights
    if (tid < 32) {
        float b0 = b_t[t * NNODE + 2 * tid];
        float b1 = b_t[t * NNODE + 2 * tid + 1];
        s_bt2[tid] = __floats2half2_rn(b0, b1);
    }
    for (int i = tid; i < NNODE * 16; i += 128) {
        int node = i >> 4, leaf = i & 15;
        s_wdh[i] = (leaf < NLEAF) ? __float2half(w_d[(size_t)t * NNODE * NLEAF + node * NLEAF + leaf])
                                  : __half(0.0f);
    }
    if (tid < 16)      s_bd16[tid] = (tid < NLEAF) ? b_d[t * NLEAF + tid] : 0.0f;
    else if (tid < 32) s_wl[tid - 16] = w_l[t * NLEAVES + tid - 16];

    // f16x2 accumulators: [mt][nt][2]
    uint32_t acc[2][8][2];
    #pragma unroll
    for (int mt = 0; mt < 2; mt++)
        #pragma unroll
        for (int nt = 0; nt < 8; nt++) { acc[mt][nt][0] = 0u; acc[mt][nt][1] = 0u; }

    // ldmatrix lane addressing (bytes; 128B rows)
    const int a_row  = wid * 32 + (lane & 15);
    const int a_colb = (lane >> 4) * 16;
    const int b_row  = (lane & 7) + ((lane >> 4) << 3);
    const int b_colb = ((lane >> 3) & 1) * 16;

    const uint8_t* gx = g_xf8 + (size_t)rb * D_FEAT;
    const uint8_t* gw = g_wf8 + (size_t)t * NNODE * D_FEAT;

    auto loadChunk = [&](int c) {
        const uint32_t aB = dsBase + (c & 1) * STAGE_BYTES;
        const uint32_t bB = aB + 16384;
        const int kc = c * 128;
        #pragma unroll
        for (int it = 0; it < 8; it++) {
            int ui = tid + it * 128;
            int r = ui >> 3, seg = ui & 7;
            cp16(aB + SWZ(r * 128 + seg * 16), gx + (size_t)r * D_FEAT + kc + seg * 16);
        }
        #pragma unroll
        for (int it = 0; it < 4; it++) {
            int ui = tid + it * 128;
            int r = ui >> 3, seg = ui & 7;
            cp16(bB + SWZ(r * 128 + seg * 16), gw + (size_t)r * D_FEAT + kc + seg * 16);
        }
        CP_COMMIT();
    };

    loadChunk(0);
    for (int c = 0; c < 4; c++) {
        if (c < 3) {
            loadChunk(c + 1);
            asm volatile("cp.async.wait_group 1;");
        } else {
            asm volatile("cp.async.wait_group 0;");
        }
        __syncthreads();

        const uint32_t aB = dsBase + (c & 1) * STAGE_BYTES;
        const uint32_t bB = aB + 16384;
        #pragma unroll
        for (int ks = 0; ks < 4; ks++) {
            const int kk = ks * 32;
            uint32_t afr[2][4];
            #pragma unroll
            for (int mt = 0; mt < 2; mt++)
                LDSM_X4(afr[mt], aB + SWZ((a_row + mt * 16) * 128 + kk + a_colb));
            uint32_t bfr[8][2];
            #pragma unroll
            for (int nq = 0; nq < 4; nq++) {
                uint32_t r4[4];
                LDSM_X4(r4, bB + SWZ((b_row + nq * 16) * 128 + kk + b_colb));
                bfr[2 * nq][0]     = r4[0]; bfr[2 * nq][1]     = r4[1];
                bfr[2 * nq + 1][0] = r4[2]; bfr[2 * nq + 1][1] = r4[3];
            }
            #pragma unroll
            for (int mt = 0; mt < 2; mt++)
                #pragma unroll
                for (int nt = 0; nt < 8; nt++)
                    MMA_FP8_F16(acc[mt][nt], afr[mt], bfr[nt]);
        }
        if (c < 3) __syncthreads();
    }

    // ---------------- epilogue (register-resident) ------------------------------
    // 1) h = relu(acc * 1/16 + bias) in f16x2, in place (C->A fragment layout reuse)
    const __half2 inv2  = __float2half2_rn(W_INV);
    const __half2 zero2 = __float2half2_rn(0.0f);
    #pragma unroll
    for (int mt = 0; mt < 2; mt++)
        #pragma unroll
        for (int nt = 0; nt < 8; nt++) {
            __half2 bias = s_bt2[nt * 4 + (lane & 3)];
            #pragma unroll
            for (int r = 0; r < 2; r++) {
                __half2 v = *(__half2*)&acc[mt][nt][r];
                v = __hmax2(__hfma2(v, inv2, bias), zero2);
                acc[mt][nt][r] = *(uint32_t*)&v;
            }
        }

    // 2) B fragments of w_d (k=node 64, n=leaf 16): bw[nt2][ks][2]
    uint32_t bw[2][4][2];
    {
        const int n = lane >> 2;
        const int kb = (lane & 3) * 2;
        #pragma unroll
        for (int nt2 = 0; nt2 < 2; nt2++)
            #pragma unroll
            for (int ks = 0; ks < 4; ks++) {
                int k0 = ks * 16 + kb;
                int nn = nt2 * 8 + n;
                __half2 lo = __halves2half2(s_wdh[k0 * 16 + nn],       s_wdh[(k0 + 1) * 16 + nn]);
                __half2 hi = __halves2half2(s_wdh[(k0 + 8) * 16 + nn], s_wdh[(k0 + 9) * 16 + nn]);
                bw[nt2][ks][0] = *(uint32_t*)&lo;
                bw[nt2][ks][1] = *(uint32_t*)&hi;
            }
    }

    // 3) logits = h @ w_d + b_d via mma.m16n8k16 (f32 accum)
    float lg[2][2][4];
    {
        const int col = (lane & 3) * 2;
        #pragma unroll
        for (int mt = 0; mt < 2; mt++)
            #pragma unroll
            for (int nt2 = 0; nt2 < 2; nt2++) {
                lg[mt][nt2][0] = s_bd16[nt2 * 8 + col];
                lg[mt][nt2][1] = s_bd16[nt2 * 8 + col + 1];
                lg[mt][nt2][2] = lg[mt][nt2][0];
                lg[mt][nt2][3] = lg[mt][nt2][1];
            }
        #pragma unroll
        for (int mt = 0; mt < 2; mt++)
            #pragma unroll
            for (int ks = 0; ks < 4; ks++) {
                #pragma unroll
                for (int nt2 = 0; nt2 < 2; nt2++)
                    MMA_F16_F32(lg[mt][nt2],
                                acc[mt][2 * ks][0], acc[mt][2 * ks][1],
                                acc[mt][2 * ks + 1][0], acc[mt][2 * ks + 1][1],
                                bw[nt2][ks][0], bw[nt2][ks][1]);
            }
    }

    // 4) sigmoid + warp-local exchange through smem (overlays dead stage-0 buffer)
    float* ps = (float*)ds;   // [128][17]
    {
        const int g   = lane >> 2;
        const int col = (lane & 3) * 2;
        #pragma unroll
        for (int mt = 0; mt < 2; mt++) {
            int r0 = wid * 32 + mt * 16 + g;
            #pragma unroll
            for (int nt2 = 0; nt2 < 2; nt2++) {
                int cc = nt2 * 8 + col;
                ps[r0 * 17 + cc]           = fast_sigmoid(lg[mt][nt2][0]);
                ps[r0 * 17 + cc + 1]       = fast_sigmoid(lg[mt][nt2][1]);
                ps[(r0 + 8) * 17 + cc]     = fast_sigmoid(lg[mt][nt2][2]);
                ps[(r0 + 8) * 17 + cc + 1] = fast_sigmoid(lg[mt][nt2][3]);
            }
        }
    }
    __syncwarp();

    // 5) routing + tanh, one row per thread (row == tid, warp-local)
    {
        const float* prow = &ps[tid * 17];
        float p[NLEAF];
        #pragma unroll
        for (int j = 0; j < NLEAF; j++) p[j] = prow[j];
        float facc = 0.0f;
        #pragma unroll
        for (int l = 0; l < NLEAVES; l++) {
            int node = 0;
            float m = 1.0f;
            #pragma unroll
            for (int d = 0; d < 4; d++) {
                int bit = (l >> (3 - d)) & 1;
                float pv = p[node];
                m *= bit ? (1.0f - pv) : pv;
                node = 2 * node + 1 + bit;
            }
            facc = fmaf(m, s_wl[l], facc);
        }
        float f = tanhf(facc + b_l[t]);
        g_fT[(size_t)(rb + tid) * T_TREES + t] = f;
    }
}

// ---------------- cumsum: one warp per batch row, MLP-prefetched ---------------
__global__ void gbdt_cumsum_kernel(const float* __restrict__ f0,
                                   float* __restrict__ out)
{
    int gwarp = (blockIdx.x * blockDim.x + threadIdx.x) >> 5;
    int lane  = threadIdx.x & 31;
    if (gwarp >= BATCH) return;

    float vals[7];
    #pragma unroll
    for (int i = 0; i < 7; i++) {
        int tt = i * 32 + lane;
        vals[i] = (tt < T_TREES) ? LR * g_fT[(size_t)gwarp * T_TREES + tt] : 0.0f;
    }

    float run = f0[0];
    if (lane == 0) out[(size_t)gwarp * (T_TREES + 1)] = run;
    #pragma unroll
    for (int i = 0; i < 7; i++) {
        float v = vals[i];
        #pragma unroll
        for (int off = 1; off < 32; off <<= 1) {
            float nv = __shfl_up_sync(0xFFFFFFFFu, v, off);
            if (lane >= off) v += nv;
        }
        int tt = i * 32 + lane;
        if (tt < T_TREES) out[(size_t)gwarp * (T_TREES + 1) + 1 + tt] = run + v;
        run += __shfl_sync(0xFFFFFFFFu, v, 31);
    }
}

// ---------------- launcher ------------------------------------------------------
extern "C" void kernel_launch(void* const* d_in, const int* in_sizes, int n_in,
                              void* d_out, int out_size)
{
    const float* x   = (const float*)d_in[0];
    const float* w_t = (const float*)d_in[2];
    const float* b_t = (const float*)d_in[3];
    const float* w_d = (const float*)d_in[4];
    const float* b_d = (const float*)d_in[5];
    const float* w_l = (const float*)d_in[6];
    const float* b_l = (const float*)d_in[7];
    const float* f_0 = (const float*)d_in[8];
    float* out = (float*)d_out;

    static bool attr_set = false;
    if (!attr_set) {
        cudaFuncSetAttribute(gbdt_main_kernel,
                             cudaFuncAttributeMaxDynamicSharedMemorySize, SMEM_DYN);
        attr_set = true;
    }

    conv_prep_kernel<<<XBLOCKS + WBLOCKS, 256>>>(x, w_t);
    gbdt_main_kernel<<<dim3(BATCH / 128, T_TREES), 128, SMEM_DYN>>>(b_t, w_d, b_d, w_l, b_l);
    gbdt_cumsum_kernel<<<(BATCH * 32 + 255) / 256, 256>>>(f_0, out);
}

// round 16
// speedup vs baseline: 1.3276x; 1.0032x over previous
#include <cuda_runtime.h>
#include <cuda_fp8.h>
#include <cuda_fp16.h>
#include <cstdint>
#include <math.h>

#define T_TREES 200
#define BATCH   2048
#define D_FEAT  512
#define NNODE   64
#define NLEAF   15
#define NLEAVES 16
#define LR      0.01f

#define W_SCALE 16.0f
#define W_INV   0.0625f

// ---------------- device scratch (no runtime allocation allowed) -------------
__device__ uint8_t g_xf8[BATCH * D_FEAT];                    // x in e4m3
__device__ uint8_t g_wf8[(size_t)T_TREES * NNODE * D_FEAT];  // w_t e4m3, [t][n][k], x16
__device__ float   g_fT[(size_t)BATCH * T_TREES];            // f transposed [b][t]

// ---------------- helpers ------------------------------------------------------
__device__ __forceinline__ uint32_t smem_u32(const void* p) {
    uint32_t a;
    asm("{ .reg .u64 t; cvta.to.shared.u64 t, %1; cvt.u32.u64 %0, t; }" : "=r"(a) : "l"(p));
    return a;
}
#define SWZ(o) ((o) ^ (((o) >> 3) & 0x70))

__device__ __forceinline__ void cp16(uint32_t dst, const void* src) {
    asm volatile("cp.async.cg.shared.global [%0], [%1], 16;" :: "r"(dst), "l"(src));
}
#define CP_COMMIT() asm volatile("cp.async.commit_group;")

#define LDSM_X4(r, addr) \
    asm volatile("ldmatrix.sync.aligned.m8n8.x4.shared.b16 {%0,%1,%2,%3}, [%4];" \
        : "=r"((r)[0]), "=r"((r)[1]), "=r"((r)[2]), "=r"((r)[3]) : "r"(addr))

// fp8 MMA with f16 accumulate (proven 20% faster than f32-accum on sm_103 legacy pipe)
#define MMA_FP8_F16(d, a, b) \
    asm volatile("mma.sync.aligned.m16n8k32.row.col.f16.e4m3.e4m3.f16 " \
        "{%0,%1}, {%2,%3,%4,%5}, {%6,%7}, {%0,%1};" \
        : "+r"((d)[0]), "+r"((d)[1]) \
        : "r"((a)[0]), "r"((a)[1]), "r"((a)[2]), "r"((a)[3]), \
          "r"((b)[0]), "r"((b)[1]))

// f16 x f16 -> f32 MMA for the stage-2 decision GEMM
#define MMA_F16_F32(d, a0, a1, a2, a3, b0, b1) \
    asm volatile("mma.sync.aligned.m16n8k16.row.col.f32.f16.f16.f32 " \
        "{%0,%1,%2,%3}, {%4,%5,%6,%7}, {%8,%9}, {%0,%1,%2,%3};" \
        : "+f"((d)[0]), "+f"((d)[1]), "+f"((d)[2]), "+f"((d)[3]) \
        : "r"(a0), "r"(a1), "r"(a2), "r"(a3), "r"(b0), "r"(b1))

__device__ __forceinline__ float fast_sigmoid(float v) {
    float th;
    asm("tanh.approx.f32 %0, %1;" : "=f"(th) : "f"(v * 0.5f));
    return fmaf(0.5f, th, 0.5f);
}

__device__ __forceinline__ uint16_t pack_e4m3x2(float lo, float hi) {
    float2 f2; f2.x = lo; f2.y = hi;
    return (uint16_t)__nv_cvt_float2_to_fp8x2(f2, __NV_SATFINITE, __NV_E4M3);
}

// ---------------- fused prep kernel --------------------------------------------
// blocks [0, 512): convert x (fp32 -> e4m3), 8 values/thread.
// blocks [512, 912): w transpose+convert, float4 granularity.
//   Thread = (t, 4-n group, 16-k chunk): 16 float4 loads (16 lanes x 16B = 256B
//   contiguous per warp transaction), 64 values in regs, 4 aligned uint4 stores.
#define XBLOCKS (BATCH * D_FEAT / 8 / 256)            // 512
#define WBLOCKS (T_TREES * 16 * 32 / 256)             // 400

__global__ void conv_prep_kernel(const float* __restrict__ x,
                                 const float* __restrict__ w_t) {
    if (blockIdx.x < XBLOCKS) {
        int i = (blockIdx.x * 256 + threadIdx.x) * 8;
        float4 v0 = *(const float4*)(x + i);
        float4 v1 = *(const float4*)(x + i + 4);
        uint32_t lo = (uint32_t)pack_e4m3x2(v0.x, v0.y) | ((uint32_t)pack_e4m3x2(v0.z, v0.w) << 16);
        uint32_t hi = (uint32_t)pack_e4m3x2(v1.x, v1.y) | ((uint32_t)pack_e4m3x2(v1.z, v1.w) << 16);
        *(uint2*)(g_xf8 + i) = make_uint2(lo, hi);
        return;
    }
    int o   = (blockIdx.x - XBLOCKS) * 256 + threadIdx.x;  // 0 .. 102399
    int n4  = o & 15;            // group of 4 n
    int k16 = (o >> 4) & 31;     // group of 16 k
    int t   = o >> 9;

    const float* src = w_t + ((size_t)t * D_FEAT + k16 * 16) * NNODE + n4 * 4;
    float4 v[16];
    #pragma unroll
    for (int j = 0; j < 16; j++) v[j] = *(const float4*)(src + j * NNODE);

    #pragma unroll
    for (int i = 0; i < 4; i++) {
        const float* e = &v[0].x + i;   // select component i across v[] via stride 4
        uint32_t outw[4];
        #pragma unroll
        for (int q = 0; q < 4; q++) {
            outw[q] = (uint32_t)pack_e4m3x2(e[(4 * q) * 4]     * W_SCALE, e[(4 * q + 1) * 4] * W_SCALE)
                    | ((uint32_t)pack_e4m3x2(e[(4 * q + 2) * 4] * W_SCALE, e[(4 * q + 3) * 4] * W_SCALE) << 16);
        }
        *(uint4*)(g_wf8 + ((size_t)t * NNODE + n4 * 4 + i) * D_FEAT + k16 * 16) = *(uint4*)outw;
    }
}

// ---------------- main fused kernel -------------------------------------------
// grid (16, 200), 128 threads (4 warps). CTA: tree t, batch rows [rb, rb+128).
// Proven-optimal shape: M=128, double-buffered 24KB stages, 4 CTAs/SM.
// Single-sync pipeline: wait -> sync -> prefetch(c+1) -> compute(c).
#define STAGE_BYTES 24576   // A 16KB + B 8KB
#define SMEM_DYN (2 * STAGE_BYTES)

__global__ void __launch_bounds__(128)
gbdt_main_kernel(const float* __restrict__ b_t, const float* __restrict__ w_d,
                 const float* __restrict__ b_d, const float* __restrict__ w_l,
                 const float* __restrict__ b_l)
{
    extern __shared__ char ds[];
    __shared__ __half2 s_bt2[32];          // bias pairs for 64 cols
    __shared__ __half  s_wdh[NNODE * 16];  // w_d f16, [node][leaf], col 15 zero
    __shared__ float   s_bd16[16];         // b_d padded
    __shared__ float   s_wl[NLEAVES];

    const int t    = blockIdx.y;
    const int rb   = blockIdx.x * 128;
    const int tid  = threadIdx.x;
    const int wid  = tid >> 5;
    const int lane = tid & 31;
    const uint32_t dsBase = smem_u32(ds);

    // per-tree small weights
    if (tid < 32) {
        float b0 = b_t[t * NNODE + 2 * tid];
        float b1 = b_t[t * NNODE + 2 * tid + 1];
        s_bt2[tid] = __floats2half2_rn(b0, b1);
    }
    for (int i = tid; i < NNODE * 16; i += 128) {
        int node = i >> 4, leaf = i & 15;
        s_wdh[i] = (leaf < NLEAF) ? __float2half(w_d[(size_t)t * NNODE * NLEAF + node * NLEAF + leaf])
                                  : __half(0.0f);
    }
    if (tid < 16)      s_bd16[tid] = (tid < NLEAF) ? b_d[t * NLEAF + tid] : 0.0f;
    else if (tid < 32) s_wl[tid - 16] = w_l[t * NLEAVES + tid - 16];

    // f16x2 accumulators: [mt][nt][2]
    uint32_t acc[2][8][2];
    #pragma unroll
    for (int mt = 0; mt < 2; mt++)
        #pragma unroll
        for (int nt = 0; nt < 8; nt++) { acc[mt][nt][0] = 0u; acc[mt][nt][1] = 0u; }

    // ldmatrix lane addressing (bytes; 128B rows)
    const int a_row  = wid * 32 + (lane & 15);
    const int a_colb = (lane >> 4) * 16;
    const int b_row  = (lane & 7) + ((lane >> 4) << 3);
    const int b_colb = ((lane >> 3) & 1) * 16;

    const uint8_t* gx = g_xf8 + (size_t)rb * D_FEAT;
    const uint8_t* gw = g_wf8 + (size_t)t * NNODE * D_FEAT;

    auto loadChunk = [&](int c) {
        const uint32_t aB = dsBase + (c & 1) * STAGE_BYTES;
        const uint32_t bB = aB + 16384;
        const int kc = c * 128;
        #pragma unroll
        for (int it = 0; it < 8; it++) {
            int ui = tid + it * 128;
            int r = ui >> 3, seg = ui & 7;
            cp16(aB + SWZ(r * 128 + seg * 16), gx + (size_t)r * D_FEAT + kc + seg * 16);
        }
        #pragma unroll
        for (int it = 0; it < 4; it++) {
            int ui = tid + it * 128;
            int r = ui >> 3, seg = ui & 7;
            cp16(bB + SWZ(r * 128 + seg * 16), gw + (size_t)r * D_FEAT + kc + seg * 16);
        }
        CP_COMMIT();
    };

    loadChunk(0);
    for (int c = 0; c < 4; c++) {
        asm volatile("cp.async.wait_group 0;");
        __syncthreads();                 // stage c ready; all warps done with stage c^1
        if (c < 3) loadChunk(c + 1);     // prefetch overlaps compute(c)

        const uint32_t aB = dsBase + (c & 1) * STAGE_BYTES;
        const uint32_t bB = aB + 16384;
        #pragma unroll
        for (int ks = 0; ks < 4; ks++) {
            const int kk = ks * 32;
            uint32_t afr[2][4];
            #pragma unroll
            for (int mt = 0; mt < 2; mt++)
                LDSM_X4(afr[mt], aB + SWZ((a_row + mt * 16) * 128 + kk + a_colb));
            uint32_t bfr[8][2];
            #pragma unroll
            for (int nq = 0; nq < 4; nq++) {
                uint32_t r4[4];
                LDSM_X4(r4, bB + SWZ((b_row + nq * 16) * 128 + kk + b_colb));
                bfr[2 * nq][0]     = r4[0]; bfr[2 * nq][1]     = r4[1];
                bfr[2 * nq + 1][0] = r4[2]; bfr[2 * nq + 1][1] = r4[3];
            }
            #pragma unroll
            for (int mt = 0; mt < 2; mt++)
                #pragma unroll
                for (int nt = 0; nt < 8; nt++)
                    MMA_FP8_F16(acc[mt][nt], afr[mt], bfr[nt]);
        }
    }

    // ---------------- epilogue (register-resident) ------------------------------
    // 1) h = relu(acc * 1/16 + bias) in f16x2, in place (C->A fragment layout reuse)
    const __half2 inv2  = __float2half2_rn(W_INV);
    const __half2 zero2 = __float2half2_rn(0.0f);
    #pragma unroll
    for (int mt = 0; mt < 2; mt++)
        #pragma unroll
        for (int nt = 0; nt < 8; nt++) {
            __half2 bias = s_bt2[nt * 4 + (lane & 3)];
            #pragma unroll
            for (int r = 0; r < 2; r++) {
                __half2 v = *(__half2*)&acc[mt][nt][r];
                v = __hmax2(__hfma2(v, inv2, bias), zero2);
                acc[mt][nt][r] = *(uint32_t*)&v;
            }
        }

    // 2) B fragments of w_d (k=node 64, n=leaf 16): bw[nt2][ks][2]
    uint32_t bw[2][4][2];
    {
        const int n = lane >> 2;
        const int kb = (lane & 3) * 2;
        #pragma unroll
        for (int nt2 = 0; nt2 < 2; nt2++)
            #pragma unroll
            for (int ks = 0; ks < 4; ks++) {
                int k0 = ks * 16 + kb;
                int nn = nt2 * 8 + n;
                __half2 lo = __halves2half2(s_wdh[k0 * 16 + nn],       s_wdh[(k0 + 1) * 16 + nn]);
                __half2 hi = __halves2half2(s_wdh[(k0 + 8) * 16 + nn], s_wdh[(k0 + 9) * 16 + nn]);
                bw[nt2][ks][0] = *(uint32_t*)&lo;
                bw[nt2][ks][1] = *(uint32_t*)&hi;
            }
    }

    // 3) logits = h @ w_d + b_d via mma.m16n8k16 (f32 accum)
    float lg[2][2][4];
    {
        const int col = (lane & 3) * 2;
        #pragma unroll
        for (int mt = 0; mt < 2; mt++)
            #pragma unroll
            for (int nt2 = 0; nt2 < 2; nt2++) {
                lg[mt][nt2][0] = s_bd16[nt2 * 8 + col];
                lg[mt][nt2][1] = s_bd16[nt2 * 8 + col + 1];
                lg[mt][nt2][2] = lg[mt][nt2][0];
                lg[mt][nt2][3] = lg[mt][nt2][1];
            }
        #pragma unroll
        for (int mt = 0; mt < 2; mt++)
            #pragma unroll
            for (int ks = 0; ks < 4; ks++) {
                #pragma unroll
                for (int nt2 = 0; nt2 < 2; nt2++)
                    MMA_F16_F32(lg[mt][nt2],
                                acc[mt][2 * ks][0], acc[mt][2 * ks][1],
                                acc[mt][2 * ks + 1][0], acc[mt][2 * ks + 1][1],
                                bw[nt2][ks][0], bw[nt2][ks][1]);
            }
    }

    // 4) sigmoid + warp-local exchange through smem (overlays dead stage-0 buffer)
    float* ps = (float*)ds;   // [128][17]; stage 0 last read in compute(2), fenced by c=3 sync
    {
        const int g   = lane >> 2;
        const int col = (lane & 3) * 2;
        #pragma unroll
        for (int mt = 0; mt < 2; mt++) {
            int r0 = wid * 32 + mt * 16 + g;
            #pragma unroll
            for (int nt2 = 0; nt2 < 2; nt2++) {
                int cc = nt2 * 8 + col;
                ps[r0 * 17 + cc]           = fast_sigmoid(lg[mt][nt2][0]);
                ps[r0 * 17 + cc + 1]       = fast_sigmoid(lg[mt][nt2][1]);
                ps[(r0 + 8) * 17 + cc]     = fast_sigmoid(lg[mt][nt2][2]);
                ps[(r0 + 8) * 17 + cc + 1] = fast_sigmoid(lg[mt][nt2][3]);
            }
        }
    }
    __syncwarp();

    // 5) routing + tanh, one row per thread (row == tid, warp-local)
    {
        const float* prow = &ps[tid * 17];
        float p[NLEAF];
        #pragma unroll
        for (int j = 0; j < NLEAF; j++) p[j] = prow[j];
        float facc = 0.0f;
        #pragma unroll
        for (int l = 0; l < NLEAVES; l++) {
            int node = 0;
            float m = 1.0f;
            #pragma unroll
            for (int d = 0; d < 4; d++) {
                int bit = (l >> (3 - d)) & 1;
                float pv = p[node];
                m *= bit ? (1.0f - pv) : pv;
                node = 2 * node + 1 + bit;
            }
            facc = fmaf(m, s_wl[l], facc);
        }
        float f = tanhf(facc + b_l[t]);
        g_fT[(size_t)(rb + tid) * T_TREES + t] = f;
    }
}

// ---------------- cumsum: one warp per batch row, MLP-prefetched ---------------
__global__ void gbdt_cumsum_kernel(const float* __restrict__ f0,
                                   float* __restrict__ out)
{
    int gwarp = (blockIdx.x * blockDim.x + threadIdx.x) >> 5;
    int lane  = threadIdx.x & 31;
    if (gwarp >= BATCH) return;

    float vals[7];
    #pragma unroll
    for (int i = 0; i < 7; i++) {
        int tt = i * 32 + lane;
        vals[i] = (tt < T_TREES) ? LR * g_fT[(size_t)gwarp * T_TREES + tt] : 0.0f;
    }

    float run = f0[0];
    if (lane == 0) out[(size_t)gwarp * (T_TREES + 1)] = run;
    #pragma unroll
    for (int i = 0; i < 7; i++) {
        float v = vals[i];
        #pragma unroll
        for (int off = 1; off < 32; off <<= 1) {
            float nv = __shfl_up_sync(0xFFFFFFFFu, v, off);
            if (lane >= off) v += nv;
        }
        int tt = i * 32 + lane;
        if (tt < T_TREES) out[(size_t)gwarp * (T_TREES + 1) + 1 + tt] = run + v;
        run += __shfl_sync(0xFFFFFFFFu, v, 31);
    }
}

// ---------------- launcher ------------------------------------------------------
extern "C" void kernel_launch(void* const* d_in, const int* in_sizes, int n_in,
                              void* d_out, int out_size)
{
    const float* x   = (const float*)d_in[0];
    const float* w_t = (const float*)d_in[2];
    const float* b_t = (const float*)d_in[3];
    const float* w_d = (const float*)d_in[4];
    const float* b_d = (const float*)d_in[5];
    const float* w_l = (const float*)d_in[6];
    const float* b_l = (const float*)d_in[7];
    const float* f_0 = (const float*)d_in[8];
    float* out = (float*)d_out;

    static bool attr_set = false;
    if (!attr_set) {
        cudaFuncSetAttribute(gbdt_main_kernel,
                             cudaFuncAttributeMaxDynamicSharedMemorySize, SMEM_DYN);
        attr_set = true;
    }

    conv_prep_kernel<<<XBLOCKS + WBLOCKS, 256>>>(x, w_t);
    gbdt_main_kernel<<<dim3(BATCH / 128, T_TREES), 128, SMEM_DYN>>>(b_t, w_d, b_d, w_l, b_l);
    gbdt_cumsum_kernel<<<(BATCH * 32 + 255) / 256, 256>>>(f_0, out);
}